// round 3
// baseline (speedup 1.0000x reference)
#include <cuda_runtime.h>
#include <math_constants.h>

// Problem constants
#define BB 2
#define CC 2048
#define NN 4096          // H*W = 64*64
#define K2C 4096         // 2*C
#define MQKV 6144        // C (Q) + C (K) + C (Vsum)

// Scratch (device globals — no allocations allowed)
__device__ float g_W[(long)MQKV * K2C];          // stacked weights [6144, 4096]
__device__ float g_bias[MQKV];
__device__ float g_QKV[(long)BB * MQKV * NN];    // Q|K|Vsum per batch
__device__ float g_S[(long)BB * NN * NN];        // pre-softmax logits

// ---------------------------------------------------------------------------
// prep: stack wq, wk, (wv_top+wv_bot) into g_W; biases into g_bias
// ---------------------------------------------------------------------------
__global__ void prep_kernel(const float* __restrict__ wq, const float* __restrict__ bq,
                            const float* __restrict__ wk, const float* __restrict__ bk,
                            const float* __restrict__ wv, const float* __restrict__ bv) {
    long i = (long)blockIdx.x * blockDim.x + threadIdx.x;
    long total = (long)MQKV * K2C;
    if (i < total) {
        int row = (int)(i >> 12);
        int col = (int)(i & 4095);
        float v;
        if (row < CC) {
            v = wq[i];
        } else if (row < 2 * CC) {
            v = wk[i - (long)CC * K2C];
        } else {
            int r = row - 2 * CC;
            v = wv[(long)r * K2C + col] + wv[(long)(r + CC) * K2C + col];
        }
        g_W[i] = v;
    }
    if (i < MQKV) {
        int row = (int)i;
        float b;
        if (row < CC)           b = bq[row];
        else if (row < 2 * CC)  b = bk[row - CC];
        else                    b = bv[row - 2 * CC] + bv[row - CC];
        g_bias[row] = b;
    }
}

// ---------------------------------------------------------------------------
// GEMM 1: QKV = g_W [6144,4096] @ X [4096,4096] + bias     (per batch)
//   X row k: k<2048 -> f_rgb[b,k,:], else f_i[b,k-2048,:]
//   Tiles 128x128x16, 256 threads, 8x8 microtile (split 4+4 to avoid conflicts)
// ---------------------------------------------------------------------------
__global__ __launch_bounds__(256, 2) void gemm_qkv_kernel(const float* __restrict__ frgb,
                                                          const float* __restrict__ fi) {
    __shared__ float As[16][132];   // As[k][m]  (W transposed)
    __shared__ float Bs[16][132];   // Bs[k][n]
    const int b  = blockIdx.z;
    const int m0 = blockIdx.y * 128;
    const int n0 = blockIdx.x * 128;
    const int tid = threadIdx.x;
    const int tx = tid & 15, ty = tid >> 4;

    float acc[8][8] = {};
    const float* xr = frgb + (long)b * CC * NN;
    const float* xi = fi   + (long)b * CC * NN;

    for (int k0 = 0; k0 < K2C; k0 += 16) {
        #pragma unroll
        for (int l = 0; l < 2; l++) {
            int idx = tid + l * 256;
            int row = idx >> 2;
            int kq  = (idx & 3) * 4;
            float4 w = *(const float4*)(g_W + (long)(m0 + row) * K2C + k0 + kq);
            As[kq + 0][row] = w.x; As[kq + 1][row] = w.y;
            As[kq + 2][row] = w.z; As[kq + 3][row] = w.w;
        }
        #pragma unroll
        for (int l = 0; l < 2; l++) {
            int idx = tid + l * 256;
            int krow = idx >> 5;
            int nq   = (idx & 31) * 4;
            int k = k0 + krow;
            const float* src = (k < CC) ? (xr + (long)k * NN) : (xi + (long)(k - CC) * NN);
            *(float4*)&Bs[krow][nq] = *(const float4*)(src + n0 + nq);
        }
        __syncthreads();
        #pragma unroll
        for (int k = 0; k < 16; k++) {
            float a[8], bb[8];
            *(float4*)&a[0]  = *(const float4*)&As[k][ty * 4];
            *(float4*)&a[4]  = *(const float4*)&As[k][ty * 4 + 64];
            *(float4*)&bb[0] = *(const float4*)&Bs[k][tx * 4];
            *(float4*)&bb[4] = *(const float4*)&Bs[k][tx * 4 + 64];
            #pragma unroll
            for (int i = 0; i < 8; i++)
                #pragma unroll
                for (int j = 0; j < 8; j++)
                    acc[i][j] += a[i] * bb[j];
        }
        __syncthreads();
    }
    float* out = g_QKV + (long)b * MQKV * NN;
    #pragma unroll
    for (int i = 0; i < 8; i++) {
        int r = m0 + ((i < 4) ? (ty * 4 + i) : (64 + ty * 4 + i - 4));
        float bias = g_bias[r];
        #pragma unroll
        for (int j = 0; j < 8; j++) {
            int c = n0 + ((j < 4) ? (tx * 4 + j) : (64 + tx * 4 + j - 4));
            out[(long)r * NN + c] = acc[i][j] + bias;
        }
    }
}

// ---------------------------------------------------------------------------
// GEMM 2: S[b][n][m] = (1/64) * sum_c Q[b][c][n] * K[b][c][m]
//   Both operands contiguous along output dims (no transpose in smem load)
// ---------------------------------------------------------------------------
__global__ __launch_bounds__(256, 2) void gemm_s_kernel() {
    __shared__ float As[16][132];   // As[c][n]
    __shared__ float Bs[16][132];   // Bs[c][m]
    const int b  = blockIdx.z;
    const int r0 = blockIdx.y * 128;   // n (output rows)
    const int m0 = blockIdx.x * 128;   // m (output cols)
    const int tid = threadIdx.x;
    const int tx = tid & 15, ty = tid >> 4;

    const float* Qb = g_QKV + (long)b * MQKV * NN;
    const float* Kb = Qb + (long)CC * NN;

    float acc[8][8] = {};
    for (int k0 = 0; k0 < CC; k0 += 16) {
        #pragma unroll
        for (int l = 0; l < 2; l++) {
            int idx = tid + l * 256;
            int krow = idx >> 5;
            int nq   = (idx & 31) * 4;
            *(float4*)&As[krow][nq] = *(const float4*)(Qb + (long)(k0 + krow) * NN + r0 + nq);
            *(float4*)&Bs[krow][nq] = *(const float4*)(Kb + (long)(k0 + krow) * NN + m0 + nq);
        }
        __syncthreads();
        #pragma unroll
        for (int k = 0; k < 16; k++) {
            float a[8], bb[8];
            *(float4*)&a[0]  = *(const float4*)&As[k][ty * 4];
            *(float4*)&a[4]  = *(const float4*)&As[k][ty * 4 + 64];
            *(float4*)&bb[0] = *(const float4*)&Bs[k][tx * 4];
            *(float4*)&bb[4] = *(const float4*)&Bs[k][tx * 4 + 64];
            #pragma unroll
            for (int i = 0; i < 8; i++)
                #pragma unroll
                for (int j = 0; j < 8; j++)
                    acc[i][j] += a[i] * bb[j];
        }
        __syncthreads();
    }
    float* Sb = g_S + (long)b * NN * NN;
    const float inv_scale = 0.015625f;   // 1/sqrt(4096)
    #pragma unroll
    for (int i = 0; i < 8; i++) {
        int r = r0 + ((i < 4) ? (ty * 4 + i) : (64 + ty * 4 + i - 4));
        #pragma unroll
        for (int j = 0; j < 8; j++) {
            int c = m0 + ((j < 4) ? (tx * 4 + j) : (64 + tx * 4 + j - 4));
            Sb[(long)r * NN + c] = acc[i][j] * inv_scale;
        }
    }
}

// ---------------------------------------------------------------------------
// softmax over last axis (m) of S -> attn (written straight into d_out)
// one block per row, 4096 elems, 16 per thread
// ---------------------------------------------------------------------------
__global__ __launch_bounds__(256) void softmax_kernel(float* __restrict__ attn) {
    const long row = blockIdx.x;
    const float* s = g_S + row * NN;
    float* o = attn + row * NN;
    const int tid = threadIdx.x;

    float v[16];
    #pragma unroll
    for (int i = 0; i < 4; i++)
        *(float4*)&v[i * 4] = *(const float4*)(s + tid * 4 + i * 1024);

    float mx = -CUDART_INF_F;
    #pragma unroll
    for (int i = 0; i < 16; i++) mx = fmaxf(mx, v[i]);

    __shared__ float red[8];
    #pragma unroll
    for (int off = 16; off > 0; off >>= 1)
        mx = fmaxf(mx, __shfl_xor_sync(0xffffffff, mx, off));
    if ((tid & 31) == 0) red[tid >> 5] = mx;
    __syncthreads();
    if (tid < 32) {
        float m = (tid < 8) ? red[tid] : -CUDART_INF_F;
        #pragma unroll
        for (int off = 4; off > 0; off >>= 1)
            m = fmaxf(m, __shfl_xor_sync(0xffffffff, m, off));
        if (tid == 0) red[0] = m;
    }
    __syncthreads();
    mx = red[0];
    __syncthreads();

    float sum = 0.f;
    #pragma unroll
    for (int i = 0; i < 16; i++) { v[i] = __expf(v[i] - mx); sum += v[i]; }
    #pragma unroll
    for (int off = 16; off > 0; off >>= 1)
        sum += __shfl_xor_sync(0xffffffff, sum, off);
    if ((tid & 31) == 0) red[tid >> 5] = sum;
    __syncthreads();
    if (tid < 32) {
        float m = (tid < 8) ? red[tid] : 0.f;
        #pragma unroll
        for (int off = 4; off > 0; off >>= 1)
            m += __shfl_xor_sync(0xffffffff, m, off);
        if (tid == 0) red[0] = m;
    }
    __syncthreads();
    float inv = 1.0f / red[0];

    #pragma unroll
    for (int i = 0; i < 16; i++) v[i] *= inv;
    #pragma unroll
    for (int i = 0; i < 4; i++)
        *(float4*)(o + tid * 4 + i * 1024) = *(const float4*)&v[i * 4];
}

// ---------------------------------------------------------------------------
// GEMM 3: f_final[b][c][n] = sum_m Vsum[b][c][m] * attn[b][n][m]
//   Both operands contiguous along the reduction dim -> transpose smem loads
// ---------------------------------------------------------------------------
__global__ __launch_bounds__(256, 2) void gemm_out_kernel(const float* __restrict__ attn,
                                                          float* __restrict__ f_final) {
    __shared__ float As[16][132];   // As[m][c]
    __shared__ float Bs[16][132];   // Bs[m][n]
    const int b  = blockIdx.z;
    const int c0 = blockIdx.y * 128;   // channel rows
    const int n0 = blockIdx.x * 128;   // pixel cols
    const int tid = threadIdx.x;
    const int tx = tid & 15, ty = tid >> 4;

    const float* Vb = g_QKV + (long)b * MQKV * NN + (long)(2 * CC) * NN;
    const float* Ab = attn + (long)b * NN * NN;

    float acc[8][8] = {};
    for (int k0 = 0; k0 < NN; k0 += 16) {
        #pragma unroll
        for (int l = 0; l < 2; l++) {
            int idx = tid + l * 256;
            int row = idx >> 2;
            int kq  = (idx & 3) * 4;
            float4 v = *(const float4*)(Vb + (long)(c0 + row) * NN + k0 + kq);
            As[kq + 0][row] = v.x; As[kq + 1][row] = v.y;
            As[kq + 2][row] = v.z; As[kq + 3][row] = v.w;
            float4 a = *(const float4*)(Ab + (long)(n0 + row) * NN + k0 + kq);
            Bs[kq + 0][row] = a.x; Bs[kq + 1][row] = a.y;
            Bs[kq + 2][row] = a.z; Bs[kq + 3][row] = a.w;
        }
        __syncthreads();
        #pragma unroll
        for (int k = 0; k < 16; k++) {
            float a[8], bb[8];
            *(float4*)&a[0]  = *(const float4*)&As[k][ty * 4];
            *(float4*)&a[4]  = *(const float4*)&As[k][ty * 4 + 64];
            *(float4*)&bb[0] = *(const float4*)&Bs[k][tx * 4];
            *(float4*)&bb[4] = *(const float4*)&Bs[k][tx * 4 + 64];
            #pragma unroll
            for (int i = 0; i < 8; i++)
                #pragma unroll
                for (int j = 0; j < 8; j++)
                    acc[i][j] += a[i] * bb[j];
        }
        __syncthreads();
    }
    #pragma unroll
    for (int i = 0; i < 8; i++) {
        int r = c0 + ((i < 4) ? (ty * 4 + i) : (64 + ty * 4 + i - 4));
        #pragma unroll
        for (int j = 0; j < 8; j++) {
            int c = n0 + ((j < 4) ? (tx * 4 + j) : (64 + tx * 4 + j - 4));
            f_final[((long)b * CC + r) * NN + c] = acc[i][j];
        }
    }
}

// ---------------------------------------------------------------------------
extern "C" void kernel_launch(void* const* d_in, const int* in_sizes, int n_in,
                              void* d_out, int out_size) {
    const float* frgb = (const float*)d_in[0];
    const float* fi   = (const float*)d_in[1];
    const float* wq   = (const float*)d_in[2];
    const float* bq   = (const float*)d_in[3];
    const float* wk   = (const float*)d_in[4];
    const float* bk   = (const float*)d_in[5];
    const float* wv   = (const float*)d_in[6];
    const float* bv   = (const float*)d_in[7];

    float* out = (float*)d_out;
    const long FSZ = (long)BB * CC * NN;      // 16,777,216
    float* f_final = out;
    float* out_rgb = out + FSZ;
    float* out_i   = out + 2 * FSZ;
    float* attn    = out + 3 * FSZ;

    long total = (long)MQKV * K2C;
    prep_kernel<<<(unsigned)((total + 255) / 256), 256>>>(wq, bq, wk, bk, wv, bv);

    dim3 g1(NN / 128, MQKV / 128, BB);
    gemm_qkv_kernel<<<g1, 256>>>(frgb, fi);

    dim3 g2(NN / 128, NN / 128, BB);
    gemm_s_kernel<<<g2, 256>>>();

    softmax_kernel<<<BB * NN, 256>>>(attn);

    dim3 g3(NN / 128, CC / 128, BB);
    gemm_out_kernel<<<g3, 256>>>(attn, f_final);

    cudaMemcpyAsync(out_rgb, frgb, FSZ * sizeof(float), cudaMemcpyDeviceToDevice);
    cudaMemcpyAsync(out_i,   fi,   FSZ * sizeof(float), cudaMemcpyDeviceToDevice);
}